// round 13
// baseline (speedup 1.0000x reference)
#include <cuda_runtime.h>
#include <cuda_fp16.h>
#include <math.h>
#include <stdint.h>

#define NN 100000
#define NE 1600000
#define KIN 256
#define HD 128

// ---------------- device scratch (no allocation allowed) ----------------
__device__ __half g_elh[(size_t)NN * HD]; // 25.6 MB fp16 el (gather target)
__device__ float g_er[(size_t)NN * HD];   // 51.2 MB
__device__ float g_s[(size_t)NE * 4];     // spill: edge weights (CSR order)
__device__ int   g_deg[NN];
__device__ int   g_off[NN + 1];
__device__ int   g_cur[NN];
__device__ int2  g_e[NE];                 // {edge_id, src_node} in CSR order
__device__ int   g_bsum[128];
__device__ int   g_node_ctr;              // work-stealing cursor

// fp16-split transposed weights: [gemm][chunk][n][hi32|lo32]
__device__ __half g_bw[2 * 8 * 128 * 64];   // 256 KB

__device__ __forceinline__ float lrelu(float x) { return x > 0.f ? x : 0.2f * x; }

__device__ __forceinline__ uint32_t smem_u32(const void* p) {
    uint32_t a;
    asm("{ .reg .u64 t; cvta.to.shared.u64 t, %1; cvt.u32.u64 %0, t; }"
        : "=r"(a) : "l"(p));
    return a;
}
__device__ __forceinline__ uint32_t SW(uint32_t x) { return x ^ ((x >> 3) & 0x70); }

__device__ __forceinline__ void hsplit(float v, unsigned short& h, unsigned short& l) {
    __half hb = __float2half_rn(v);
    float r = v - __half2float(hb);
    __half lb = __float2half_rn(r);
    h = __half_as_ushort(hb);
    l = __half_as_ushort(lb);
}

__device__ __forceinline__ void ldm_x4(uint32_t& r0, uint32_t& r1, uint32_t& r2,
                                       uint32_t& r3, uint32_t a) {
    asm volatile("ldmatrix.sync.aligned.m8n8.x4.shared.b16 {%0,%1,%2,%3}, [%4];"
                 : "=r"(r0), "=r"(r1), "=r"(r2), "=r"(r3) : "r"(a));
}
__device__ __forceinline__ void ldm_x2(uint32_t& r0, uint32_t& r1, uint32_t a) {
    asm volatile("ldmatrix.sync.aligned.m8n8.x2.shared.b16 {%0,%1}, [%2];"
                 : "=r"(r0), "=r"(r1) : "r"(a));
}
__device__ __forceinline__ void mma_f16(float* d, const uint32_t* a,
                                        uint32_t b0, uint32_t b1) {
    asm volatile(
        "mma.sync.aligned.m16n8k16.row.col.f32.f16.f16.f32 "
        "{%0,%1,%2,%3}, {%4,%5,%6,%7}, {%8,%9}, {%0,%1,%2,%3};"
        : "+f"(d[0]), "+f"(d[1]), "+f"(d[2]), "+f"(d[3])
        : "r"(a[0]), "r"(a[1]), "r"(a[2]), "r"(a[3]), "r"(b0), "r"(b1));
}
__device__ __forceinline__ void cp16(uint32_t dst, const void* src) {
    asm volatile("cp.async.cg.shared.global [%0], [%1], 16;"
                 :: "r"(dst), "l"(src) : "memory");
}
__device__ __forceinline__ void cp_commit() {
    asm volatile("cp.async.commit_group;" ::: "memory");
}
__device__ __forceinline__ void cp_wait0() {
    asm volatile("cp.async.wait_group 0;" ::: "memory");
}

// ---------------- weight transpose + fp16 split ----------------
__global__ void wsplit_kernel(const float* __restrict__ w_src,
                              const float* __restrict__ w_dst) {
    int i = blockIdx.x * blockDim.x + threadIdx.x;
    if (i >= 2 * 8 * 128 * 32) return;
    int g  = i >> 15;
    int c  = (i >> 12) & 7;
    int n  = (i >> 5) & 127;
    int kk = i & 31;
    const float* W = g ? w_dst : w_src;
    float v = W[(size_t)(c * 32 + kk) * HD + n];
    unsigned short h, l;
    hsplit(v, h, l);
    __half* row = g_bw + ((size_t)(g * 8 + c) * 128 + n) * 64;
    row[kk]      = __ushort_as_half(h);
    row[32 + kk] = __ushort_as_half(l);
}

// --------- fused dual GEMM via mma.sync fp16 (A exact 2-term, B hi) -------
#define STAGE_BYTES 49152
#define SM_TOT (2 * STAGE_BYTES + 1024)

__global__ void __launch_bounds__(512) gemm2_kernel(const float* __restrict__ x,
                                                    const float* __restrict__ b_src,
                                                    const float* __restrict__ b_dst) {
    extern __shared__ char smem_raw[];
    char* smem = (char*)(((uintptr_t)smem_raw + 1023) & ~(uintptr_t)1023);
    const uint32_t sb = smem_u32(smem);

    const int tid  = threadIdx.x;
    const int w    = tid >> 5;
    const int lane = tid & 31;
    const int m0   = blockIdx.x * 128;

    const int wm   = (w & 1) * 64;
    const int wnc  = (w >> 1) * 32;
    const int gm   = wnc >> 7;          // 0 = el, 1 = er
    const int wn   = wnc & 127;

    float acc[4][4][4];
#pragma unroll
    for (int a = 0; a < 4; a++)
#pragma unroll
        for (int b = 0; b < 4; b++)
#pragma unroll
            for (int d = 0; d < 4; d++) acc[a][b][d] = 0.f;

    const uint32_t a_base = (uint32_t)((wm + ((lane >> 3) & 1) * 8 + (lane & 7)) * 128 +
                                       ((lane >> 4) & 1) * 16);
    const uint32_t b_base = (uint32_t)(gm * 16384 + (wn + (lane & 7)) * 128 +
                                       ((lane & 8) ? 16 : 0));

    const int ar  = tid >> 2;
    const int aks = (tid & 3) * 8;
    const int gr  = m0 + ar;
    const bool aok = gr < NN;
    const uint32_t a_sts = (uint32_t)(ar * 128 + (tid & 3) * 16);

    float4 f0, f1;

    auto loadA = [&](int c) {
        if (aok) {
            const float4* p = (const float4*)(x + (size_t)gr * KIN + c * 32 + aks);
            f0 = p[0];
            f1 = p[1];
        } else {
            f0 = make_float4(0.f, 0.f, 0.f, 0.f);
            f1 = f0;
        }
    };
    auto stsA = [&](int buf) {
        float v[8] = {f0.x, f0.y, f0.z, f0.w, f1.x, f1.y, f1.z, f1.w};
        unsigned short h[8], l[8];
#pragma unroll
        for (int i = 0; i < 8; i++) hsplit(v[i], h[i], l[i]);
        uint4 uh, ul;
        uh.x = (uint32_t)h[0] | ((uint32_t)h[1] << 16);
        uh.y = (uint32_t)h[2] | ((uint32_t)h[3] << 16);
        uh.z = (uint32_t)h[4] | ((uint32_t)h[5] << 16);
        uh.w = (uint32_t)h[6] | ((uint32_t)h[7] << 16);
        ul.x = (uint32_t)l[0] | ((uint32_t)l[1] << 16);
        ul.y = (uint32_t)l[2] | ((uint32_t)l[3] << 16);
        ul.z = (uint32_t)l[4] | ((uint32_t)l[5] << 16);
        ul.w = (uint32_t)l[6] | ((uint32_t)l[7] << 16);
        char* base = smem + buf * STAGE_BYTES;
        *(uint4*)(base + SW(a_sts))      = uh;
        *(uint4*)(base + SW(a_sts + 64)) = ul;
    };
    // copy only the hi halves of B rows (bytes [0,64) of each 128B row)
    auto cpB = [&](int c, int buf) {
        const uint32_t dstb = sb + buf * STAGE_BYTES + 16384;
#pragma unroll
        for (int p = 0; p < 2; p++) {
            int q   = tid + 512 * p;
            int g   = q >> 9;
            int rem = q & 511;
            uint32_t off = (uint32_t)(g * 16384 + (rem >> 2) * 128 + (rem & 3) * 16);
            const char* src = (const char*)g_bw + (size_t)(g * 8 + c) * 16384 +
                              (rem >> 2) * 128 + (rem & 3) * 16;
            cp16(dstb + SW(off), src);
        }
    };

    loadA(0);
    cpB(0, 0);
    cp_commit();
    stsA(0);
    cp_wait0();
    __syncthreads();

    for (int c = 0; c < 8; c++) {
        const uint32_t stg = sb + (uint32_t)(c & 1) * STAGE_BYTES;
        if (c < 7) {
            loadA(c + 1);
            cpB(c + 1, (c + 1) & 1);
            cp_commit();
        }
#pragma unroll
        for (int kh = 0; kh < 2; kh++) {
            uint32_t aH[4][4], aL[4][4];
#pragma unroll
            for (int mt = 0; mt < 4; mt++) {
                uint32_t off = a_base + mt * 2048 + kh * 32;
                ldm_x4(aH[mt][0], aH[mt][1], aH[mt][2], aH[mt][3], stg + SW(off));
                ldm_x4(aL[mt][0], aL[mt][1], aL[mt][2], aL[mt][3], stg + SW(off + 64));
            }
#pragma unroll
            for (int nt = 0; nt < 4; nt++) {
                uint32_t offB = b_base + nt * 1024 + kh * 32;
                uint32_t bh0, bh1;
                ldm_x2(bh0, bh1, stg + 16384 + SW(offB));
#pragma unroll
                for (int mt = 0; mt < 4; mt++) {
                    mma_f16(acc[mt][nt], aH[mt], bh0, bh1);
                    mma_f16(acc[mt][nt], aL[mt], bh0, bh1);
                }
            }
        }
        if (c < 7) {
            stsA((c + 1) & 1);
            cp_wait0();
        }
        __syncthreads();
    }

    const float* bias = gm ? b_dst : b_src;
#pragma unroll
    for (int nt = 0; nt < 4; nt++) {
        int n = wn + nt * 8 + (lane & 3) * 2;
        float b0v = bias[n];
        float b1v = bias[n + 1];
#pragma unroll
        for (int mt = 0; mt < 4; mt++) {
            int m = m0 + wm + mt * 16 + (lane >> 2);
            if (gm) {
                if (m < NN) {
                    float2 o = make_float2(acc[mt][nt][0] + b0v, acc[mt][nt][1] + b1v);
                    *(float2*)(g_er + (size_t)m * HD + n) = o;
                }
                if (m + 8 < NN) {
                    float2 o = make_float2(acc[mt][nt][2] + b0v, acc[mt][nt][3] + b1v);
                    *(float2*)(g_er + (size_t)(m + 8) * HD + n) = o;
                }
            } else {
                if (m < NN) {
                    __half2 o = __floats2half2_rn(acc[mt][nt][0] + b0v,
                                                  acc[mt][nt][1] + b1v);
                    *(__half2*)(g_elh + (size_t)m * HD + n) = o;
                }
                if (m + 8 < NN) {
                    __half2 o = __floats2half2_rn(acc[mt][nt][2] + b0v,
                                                  acc[mt][nt][3] + b1v);
                    *(__half2*)(g_elh + (size_t)(m + 8) * HD + n) = o;
                }
            }
        }
    }
}

// ---------------- CSR build ----------------
__global__ void zero_deg_kernel() {
    int i = blockIdx.x * blockDim.x + threadIdx.x;
    if (i < NN) g_deg[i] = 0;
}

__global__ void count_kernel(const int* __restrict__ dst) {
    int e4 = (blockIdx.x * blockDim.x + threadIdx.x) * 4;
    if (e4 < NE) {
        int4 d = *(const int4*)(dst + e4);
        atomicAdd(&g_deg[d.x], 1);
        atomicAdd(&g_deg[d.y], 1);
        atomicAdd(&g_deg[d.z], 1);
        atomicAdd(&g_deg[d.w], 1);
    }
}

__global__ void scan1_kernel() {   // 98 blocks x 1024
    __shared__ int sm[1024];
    int i = blockIdx.x * 1024 + threadIdx.x;
    int v = (i < NN) ? g_deg[i] : 0;
    sm[threadIdx.x] = v;
    __syncthreads();
    for (int off = 1; off < 1024; off <<= 1) {
        int t = (threadIdx.x >= off) ? sm[threadIdx.x - off] : 0;
        __syncthreads();
        sm[threadIdx.x] += t;
        __syncthreads();
    }
    if (i < NN) g_off[i] = sm[threadIdx.x] - v;   // exclusive
    if (threadIdx.x == 1023) g_bsum[blockIdx.x] = sm[1023];
}

__global__ void scan2_kernel() {   // 1 block x 128
    __shared__ int sm[128];
    int v = (threadIdx.x < 98) ? g_bsum[threadIdx.x] : 0;
    sm[threadIdx.x] = v;
    __syncthreads();
    for (int off = 1; off < 128; off <<= 1) {
        int t = (threadIdx.x >= off) ? sm[threadIdx.x - off] : 0;
        __syncthreads();
        sm[threadIdx.x] += t;
        __syncthreads();
    }
    if (threadIdx.x < 98) g_bsum[threadIdx.x] = sm[threadIdx.x] - v;
}

__global__ void scan3_kernel() {   // 98 blocks x 1024
    int i = blockIdx.x * 1024 + threadIdx.x;
    if (i < NN) {
        int o = g_off[i] + g_bsum[i >> 10];
        g_off[i] = o;
        g_cur[i] = o;
    }
    if (i == 0) {
        g_off[NN] = NE;
        g_node_ctr = 0;   // reset work-stealing cursor (runs before node_kernel)
    }
}

__global__ void fill_kernel(const int* __restrict__ src, const int* __restrict__ dst) {
    int e4 = (blockIdx.x * blockDim.x + threadIdx.x) * 4;
    if (e4 < NE) {
        int4 d = *(const int4*)(dst + e4);
        int4 s = *(const int4*)(src + e4);
        int p;
        p = atomicAdd(&g_cur[d.x], 1); g_e[p] = make_int2(e4 + 0, s.x);
        p = atomicAdd(&g_cur[d.y], 1); g_e[p] = make_int2(e4 + 1, s.y);
        p = atomicAdd(&g_cur[d.z], 1); g_e[p] = make_int2(e4 + 2, s.z);
        p = atomicAdd(&g_cur[d.w], 1); g_e[p] = make_int2(e4 + 3, s.w);
    }
}

// ------- pull-based softmax aggregation + fused edge output --------
// Persistent warps + work stealing with NEXT-NODE prefetch (steal + er row
// loaded during current node). Edge loop: 16 lanes/edge, 2 edges/iter, rows
// prefetched 2 pairs deep, indices 3 pairs deep.
// Lane layout: sub = lane>>4, h = (lane>>2)&3, q = lane&3, doff = h*32+q*8.
#define WCAP 64
#define NODE_BLOCKS 592
__global__ void __launch_bounds__(256) node_kernel(const float* __restrict__ attn,
                                                   float* __restrict__ out) {
    __shared__ float4 ws[8][WCAP];   // per-CSR-slot weights [4 heads]
    int lane = threadIdx.x & 31;
    int wi   = (threadIdx.x >> 5) & 7;
    const int sub = lane >> 4;
    const int h   = (lane >> 2) & 3;
    const int q   = lane & 3;
    const int doff = h * 32 + q * 8;

    const float4 av0 = *(const float4*)&attn[doff];
    const float4 av1 = *(const float4*)&attn[doff + 4];

    auto steal = [&]() -> int {
        int t = 0;
        if (lane == 0) t = atomicAdd(&g_node_ctr, 1);
        return __shfl_sync(0xffffffffu, t, 0);
    };

    int v = steal();
    if (v >= NN) return;
    float4 rv0 = *(const float4*)&g_er[(size_t)v * HD + doff];
    float4 rv1 = *(const float4*)&g_er[(size_t)v * HD + doff + 4];

    while (v < NN) {
        // prefetch next node id + its er row while we process v
        int vn = steal();
        float4 rv0n = make_float4(0.f, 0.f, 0.f, 0.f), rv1n = rv0n;
        if (vn < NN) {
            rv0n = *(const float4*)&g_er[(size_t)vn * HD + doff];
            rv1n = *(const float4*)&g_er[(size_t)vn * HD + doff + 4];
        }

        const int beg = g_off[v];
        const int end = g_off[v + 1];
        const int npair = (end - beg + 1) >> 1;

        float lsum = 0.f;
        float4 acc0 = make_float4(0.f, 0.f, 0.f, 0.f);
        float4 acc1 = make_float4(0.f, 0.f, 0.f, 0.f);

        // pipeline state: rows for pairs t (raw0) and t+1 (raw1); index for t+2
        bool ok0 = (beg + sub) < end;
        bool ok1 = (beg + 2 + sub) < end;
        bool ok2 = (beg + 4 + sub) < end;
        int s2 = 0;
        uint4 raw0 = make_uint4(0u, 0u, 0u, 0u), raw1 = raw0;
        if (ok0) {
            int s0 = g_e[beg + sub].y;
            raw0 = *(const uint4*)(g_elh + (size_t)s0 * HD + doff);
        }
        if (ok1) {
            int s1 = g_e[beg + 2 + sub].y;
            raw1 = *(const uint4*)(g_elh + (size_t)s1 * HD + doff);
        }
        if (ok2) s2 = g_e[beg + 4 + sub].y;

        for (int t = 0; t < npair; t++) {
            // prefetch row t+2, index t+3
            uint4 nraw = make_uint4(0u, 0u, 0u, 0u);
            bool ok3 = (beg + 2 * (t + 3) + sub) < end;
            int s3 = 0;
            if (ok2) nraw = *(const uint4*)(g_elh + (size_t)s2 * HD + doff);
            if (ok3) s3 = g_e[beg + 2 * (t + 3) + sub].y;

            float2 a0 = __half22float2(*(__half2*)&raw0.x);
            float2 a1 = __half22float2(*(__half2*)&raw0.y);
            float2 a2 = __half22float2(*(__half2*)&raw0.z);
            float2 a3 = __half22float2(*(__half2*)&raw0.w);
            float4 lu0 = make_float4(a0.x, a0.y, a1.x, a1.y);
            float4 lu1 = make_float4(a2.x, a2.y, a3.x, a3.y);

            float p = lrelu(lu0.x + rv0.x) * av0.x;
            p = fmaf(lrelu(lu0.y + rv0.y), av0.y, p);
            p = fmaf(lrelu(lu0.z + rv0.z), av0.z, p);
            p = fmaf(lrelu(lu0.w + rv0.w), av0.w, p);
            p = fmaf(lrelu(lu1.x + rv1.x), av1.x, p);
            p = fmaf(lrelu(lu1.y + rv1.y), av1.y, p);
            p = fmaf(lrelu(lu1.z + rv1.z), av1.z, p);
            p = fmaf(lrelu(lu1.w + rv1.w), av1.w, p);
            p += __shfl_xor_sync(0xffffffffu, p, 1);
            p += __shfl_xor_sync(0xffffffffu, p, 2);

            float ww = ok0 ? __expf(p) : 0.f;

            if (q == 0 && ok0) {
                int pos = 2 * t + sub;
                if (pos < WCAP) ((float*)&ws[wi][pos])[h] = ww;
                else            g_s[(size_t)(beg + pos) * 4 + h] = ww;
            }

            lsum += ww;
            acc0.x = fmaf(ww, lu0.x, acc0.x);
            acc0.y = fmaf(ww, lu0.y, acc0.y);
            acc0.z = fmaf(ww, lu0.z, acc0.z);
            acc0.w = fmaf(ww, lu0.w, acc0.w);
            acc1.x = fmaf(ww, lu1.x, acc1.x);
            acc1.y = fmaf(ww, lu1.y, acc1.y);
            acc1.z = fmaf(ww, lu1.z, acc1.z);
            acc1.w = fmaf(ww, lu1.w, acc1.w);

            raw0 = raw1; raw1 = nraw;
            ok0 = ok1; ok1 = ok2; ok2 = ok3; s2 = s3;
        }

        // ---- combine the two edge-halves (sub) ----
        acc0.x += __shfl_xor_sync(0xffffffffu, acc0.x, 16);
        acc0.y += __shfl_xor_sync(0xffffffffu, acc0.y, 16);
        acc0.z += __shfl_xor_sync(0xffffffffu, acc0.z, 16);
        acc0.w += __shfl_xor_sync(0xffffffffu, acc0.w, 16);
        acc1.x += __shfl_xor_sync(0xffffffffu, acc1.x, 16);
        acc1.y += __shfl_xor_sync(0xffffffffu, acc1.y, 16);
        acc1.z += __shfl_xor_sync(0xffffffffu, acc1.z, 16);
        acc1.w += __shfl_xor_sync(0xffffffffu, acc1.w, 16);
        lsum   += __shfl_xor_sync(0xffffffffu, lsum, 16);

        float inv = (lsum > 0.f) ? (1.0f / lsum) : 0.f;
        float4 r0, r1;
        r0.x = acc0.x * inv; r0.y = acc0.y * inv;
        r0.z = acc0.z * inv; r0.w = acc0.w * inv;
        r1.x = acc1.x * inv; r1.y = acc1.y * inv;
        r1.z = acc1.z * inv; r1.w = acc1.w * inv;

        // ---- mean over heads: sum across h bits (xor 4, 8) ----
        r0.x += __shfl_xor_sync(0xffffffffu, r0.x, 4);
        r0.y += __shfl_xor_sync(0xffffffffu, r0.y, 4);
        r0.z += __shfl_xor_sync(0xffffffffu, r0.z, 4);
        r0.w += __shfl_xor_sync(0xffffffffu, r0.w, 4);
        r1.x += __shfl_xor_sync(0xffffffffu, r1.x, 4);
        r1.y += __shfl_xor_sync(0xffffffffu, r1.y, 4);
        r1.z += __shfl_xor_sync(0xffffffffu, r1.z, 4);
        r1.w += __shfl_xor_sync(0xffffffffu, r1.w, 4);
        r0.x += __shfl_xor_sync(0xffffffffu, r0.x, 8);
        r0.y += __shfl_xor_sync(0xffffffffu, r0.y, 8);
        r0.z += __shfl_xor_sync(0xffffffffu, r0.z, 8);
        r0.w += __shfl_xor_sync(0xffffffffu, r0.w, 8);
        r1.x += __shfl_xor_sync(0xffffffffu, r1.x, 8);
        r1.y += __shfl_xor_sync(0xffffffffu, r1.y, 8);
        r1.z += __shfl_xor_sync(0xffffffffu, r1.z, 8);
        r1.w += __shfl_xor_sync(0xffffffffu, r1.w, 8);

        if (lane < 4) {   // sub==0, h==0, q=lane
            float4 o0, o1;
            o0.x = r0.x * 0.25f; o0.y = r0.y * 0.25f;
            o0.z = r0.z * 0.25f; o0.w = r0.w * 0.25f;
            o1.x = r1.x * 0.25f; o1.y = r1.y * 0.25f;
            o1.z = r1.z * 0.25f; o1.w = r1.w * 0.25f;
            *(float4*)&out[(size_t)v * 32 + q * 8]     = o0;
            *(float4*)&out[(size_t)v * 32 + q * 8 + 4] = o1;
        }

        // ---- fused per-edge attention mean (phase 2) ----
        __syncwarp();
        float l0 = __shfl_sync(0xffffffffu, lsum, 0);    // head 0
        float l1 = __shfl_sync(0xffffffffu, lsum, 4);    // head 1
        float l2 = __shfl_sync(0xffffffffu, lsum, 8);    // head 2
        float l3 = __shfl_sync(0xffffffffu, lsum, 12);   // head 3
        const float i0 = (l0 > 0.f) ? 0.25f / l0 : 0.f;
        const float i1 = (l1 > 0.f) ? 0.25f / l1 : 0.f;
        const float i2 = (l2 > 0.f) ? 0.25f / l2 : 0.f;
        const float i3 = (l3 > 0.f) ? 0.25f / l3 : 0.f;

        for (int idx = beg + lane; idx < end; idx += 32) {
            int pos = idx - beg;
            float4 w4 = (pos < WCAP) ? ws[wi][pos]
                                     : *(const float4*)&g_s[(size_t)idx * 4];
            int eid = g_e[idx].x;
            float am = w4.x * i0;
            am = fmaf(w4.y, i1, am);
            am = fmaf(w4.z, i2, am);
            am = fmaf(w4.w, i3, am);
            out[(size_t)NN * 32 + eid] = am;
        }
        __syncwarp();   // ws reuse safety before next stolen node

        v = vn;
        rv0 = rv0n;
        rv1 = rv1n;
    }
}

// ---------------- launch ----------------
extern "C" void kernel_launch(void* const* d_in, const int* in_sizes, int n_in,
                              void* d_out, int out_size) {
    const float* x     = (const float*)d_in[0];
    const float* w_src = (const float*)d_in[1];
    const float* b_src = (const float*)d_in[2];
    const float* w_dst = (const float*)d_in[3];
    const float* b_dst = (const float*)d_in[4];
    const float* attn  = (const float*)d_in[5];
    const int*   src   = (const int*)d_in[6];
    const int*   dst   = (const int*)d_in[7];
    float* out = (float*)d_out;

    cudaFuncSetAttribute(gemm2_kernel, cudaFuncAttributeMaxDynamicSharedMemorySize, SM_TOT);

    cudaStream_t s2;
    cudaStreamCreateWithFlags(&s2, cudaStreamNonBlocking);
    cudaEvent_t evFork, evJoin;
    cudaEventCreateWithFlags(&evFork, cudaEventDisableTiming);
    cudaEventCreateWithFlags(&evJoin, cudaEventDisableTiming);

    cudaEventRecord(evFork, 0);
    cudaStreamWaitEvent(s2, evFork, 0);

    // stream 0: projection GEMM path
    wsplit_kernel<<<(2 * 8 * 128 * 32 + 255) / 256, 256>>>(w_src, w_dst);
    const int gemm_blocks = (NN + 127) / 128;     // 782
    gemm2_kernel<<<gemm_blocks, 512, SM_TOT>>>(x, b_src, b_dst);

    // stream s2: CSR build path
    zero_deg_kernel<<<(NN + 255) / 256, 256, 0, s2>>>();
    count_kernel<<<(NE / 4 + 255) / 256, 256, 0, s2>>>(dst);
    scan1_kernel<<<98, 1024, 0, s2>>>();
    scan2_kernel<<<1, 128, 0, s2>>>();
    scan3_kernel<<<98, 1024, 0, s2>>>();
    fill_kernel<<<(NE / 4 + 255) / 256, 256, 0, s2>>>(src, dst);

    cudaEventRecord(evJoin, s2);
    cudaStreamWaitEvent(0, evJoin, 0);

    node_kernel<<<NODE_BLOCKS, 256>>>(attn, out);

    cudaEventDestroy(evFork);
    cudaEventDestroy(evJoin);
    cudaStreamDestroy(s2);
}

// round 14
// speedup vs baseline: 1.0711x; 1.0711x over previous
#include <cuda_runtime.h>
#include <cuda_fp16.h>
#include <math.h>
#include <stdint.h>

#define NN 100000
#define NE 1600000
#define KIN 256
#define HD 128

// ---------------- device scratch (no allocation allowed) ----------------
__device__ __half g_elh[(size_t)NN * HD]; // 25.6 MB fp16 el (gather target)
__device__ __half g_erh[(size_t)NN * HD]; // 25.6 MB fp16 er
__device__ float g_s[(size_t)NE * 4];     // spill: edge weights (CSR order)
__device__ int   g_deg[NN];
__device__ int   g_off[NN + 1];
__device__ int   g_cur[NN];
__device__ int2  g_e[NE];                 // {edge_id, src_node} in CSR order
__device__ int   g_bsum[128];
__device__ int   g_node_ctr;              // work-stealing cursor

// fp16-split transposed weights: [gemm][chunk][n][hi32|lo32]
__device__ __half g_bw[2 * 8 * 128 * 64];   // 256 KB

__device__ __forceinline__ float lrelu(float x) { return x > 0.f ? x : 0.2f * x; }

__device__ __forceinline__ uint32_t smem_u32(const void* p) {
    uint32_t a;
    asm("{ .reg .u64 t; cvta.to.shared.u64 t, %1; cvt.u32.u64 %0, t; }"
        : "=r"(a) : "l"(p));
    return a;
}
__device__ __forceinline__ uint32_t SW(uint32_t x) { return x ^ ((x >> 3) & 0x70); }

__device__ __forceinline__ void hsplit(float v, unsigned short& h, unsigned short& l) {
    __half hb = __float2half_rn(v);
    float r = v - __half2float(hb);
    __half lb = __float2half_rn(r);
    h = __half_as_ushort(hb);
    l = __half_as_ushort(lb);
}

__device__ __forceinline__ void ldm_x4(uint32_t& r0, uint32_t& r1, uint32_t& r2,
                                       uint32_t& r3, uint32_t a) {
    asm volatile("ldmatrix.sync.aligned.m8n8.x4.shared.b16 {%0,%1,%2,%3}, [%4];"
                 : "=r"(r0), "=r"(r1), "=r"(r2), "=r"(r3) : "r"(a));
}
__device__ __forceinline__ void ldm_x2(uint32_t& r0, uint32_t& r1, uint32_t a) {
    asm volatile("ldmatrix.sync.aligned.m8n8.x2.shared.b16 {%0,%1}, [%2];"
                 : "=r"(r0), "=r"(r1) : "r"(a));
}
__device__ __forceinline__ void mma_f16(float* d, const uint32_t* a,
                                        uint32_t b0, uint32_t b1) {
    asm volatile(
        "mma.sync.aligned.m16n8k16.row.col.f32.f16.f16.f32 "
        "{%0,%1,%2,%3}, {%4,%5,%6,%7}, {%8,%9}, {%0,%1,%2,%3};"
        : "+f"(d[0]), "+f"(d[1]), "+f"(d[2]), "+f"(d[3])
        : "r"(a[0]), "r"(a[1]), "r"(a[2]), "r"(a[3]), "r"(b0), "r"(b1));
}
__device__ __forceinline__ void cp16(uint32_t dst, const void* src) {
    asm volatile("cp.async.cg.shared.global [%0], [%1], 16;"
                 :: "r"(dst), "l"(src) : "memory");
}
__device__ __forceinline__ void cp_commit() {
    asm volatile("cp.async.commit_group;" ::: "memory");
}
__device__ __forceinline__ void cp_wait0() {
    asm volatile("cp.async.wait_group 0;" ::: "memory");
}

// ---------------- weight transpose + fp16 split ----------------
__global__ void wsplit_kernel(const float* __restrict__ w_src,
                              const float* __restrict__ w_dst) {
    int i = blockIdx.x * blockDim.x + threadIdx.x;
    if (i >= 2 * 8 * 128 * 32) return;
    int g  = i >> 15;
    int c  = (i >> 12) & 7;
    int n  = (i >> 5) & 127;
    int kk = i & 31;
    const float* W = g ? w_dst : w_src;
    float v = W[(size_t)(c * 32 + kk) * HD + n];
    unsigned short h, l;
    hsplit(v, h, l);
    __half* row = g_bw + ((size_t)(g * 8 + c) * 128 + n) * 64;
    row[kk]      = __ushort_as_half(h);
    row[32 + kk] = __ushort_as_half(l);
}

// --------- fused dual GEMM via mma.sync fp16 (A exact 2-term, B hi) -------
#define STAGE_BYTES 49152
#define SM_TOT (2 * STAGE_BYTES + 1024)

__global__ void __launch_bounds__(512) gemm2_kernel(const float* __restrict__ x,
                                                    const float* __restrict__ b_src,
                                                    const float* __restrict__ b_dst) {
    extern __shared__ char smem_raw[];
    char* smem = (char*)(((uintptr_t)smem_raw + 1023) & ~(uintptr_t)1023);
    const uint32_t sb = smem_u32(smem);

    const int tid  = threadIdx.x;
    const int w    = tid >> 5;
    const int lane = tid & 31;
    const int m0   = blockIdx.x * 128;

    const int wm   = (w & 1) * 64;
    const int wnc  = (w >> 1) * 32;
    const int gm   = wnc >> 7;          // 0 = el, 1 = er
    const int wn   = wnc & 127;

    float acc[4][4][4];
#pragma unroll
    for (int a = 0; a < 4; a++)
#pragma unroll
        for (int b = 0; b < 4; b++)
#pragma unroll
            for (int d = 0; d < 4; d++) acc[a][b][d] = 0.f;

    const uint32_t a_base = (uint32_t)((wm + ((lane >> 3) & 1) * 8 + (lane & 7)) * 128 +
                                       ((lane >> 4) & 1) * 16);
    const uint32_t b_base = (uint32_t)(gm * 16384 + (wn + (lane & 7)) * 128 +
                                       ((lane & 8) ? 16 : 0));

    const int ar  = tid >> 2;
    const int aks = (tid & 3) * 8;
    const int gr  = m0 + ar;
    const bool aok = gr < NN;
    const uint32_t a_sts = (uint32_t)(ar * 128 + (tid & 3) * 16);

    float4 f0, f1;

    auto loadA = [&](int c) {
        if (aok) {
            const float4* p = (const float4*)(x + (size_t)gr * KIN + c * 32 + aks);
            f0 = p[0];
            f1 = p[1];
        } else {
            f0 = make_float4(0.f, 0.f, 0.f, 0.f);
            f1 = f0;
        }
    };
    auto stsA = [&](int buf) {
        float v[8] = {f0.x, f0.y, f0.z, f0.w, f1.x, f1.y, f1.z, f1.w};
        unsigned short h[8], l[8];
#pragma unroll
        for (int i = 0; i < 8; i++) hsplit(v[i], h[i], l[i]);
        uint4 uh, ul;
        uh.x = (uint32_t)h[0] | ((uint32_t)h[1] << 16);
        uh.y = (uint32_t)h[2] | ((uint32_t)h[3] << 16);
        uh.z = (uint32_t)h[4] | ((uint32_t)h[5] << 16);
        uh.w = (uint32_t)h[6] | ((uint32_t)h[7] << 16);
        ul.x = (uint32_t)l[0] | ((uint32_t)l[1] << 16);
        ul.y = (uint32_t)l[2] | ((uint32_t)l[3] << 16);
        ul.z = (uint32_t)l[4] | ((uint32_t)l[5] << 16);
        ul.w = (uint32_t)l[6] | ((uint32_t)l[7] << 16);
        char* base = smem + buf * STAGE_BYTES;
        *(uint4*)(base + SW(a_sts))      = uh;
        *(uint4*)(base + SW(a_sts + 64)) = ul;
    };
    // copy only the hi halves of B rows (bytes [0,64) of each 128B row)
    auto cpB = [&](int c, int buf) {
        const uint32_t dstb = sb + buf * STAGE_BYTES + 16384;
#pragma unroll
        for (int p = 0; p < 2; p++) {
            int q   = tid + 512 * p;
            int g   = q >> 9;
            int rem = q & 511;
            uint32_t off = (uint32_t)(g * 16384 + (rem >> 2) * 128 + (rem & 3) * 16);
            const char* src = (const char*)g_bw + (size_t)(g * 8 + c) * 16384 +
                              (rem >> 2) * 128 + (rem & 3) * 16;
            cp16(dstb + SW(off), src);
        }
    };

    loadA(0);
    cpB(0, 0);
    cp_commit();
    stsA(0);
    cp_wait0();
    __syncthreads();

    for (int c = 0; c < 8; c++) {
        const uint32_t stg = sb + (uint32_t)(c & 1) * STAGE_BYTES;
        if (c < 7) {
            loadA(c + 1);
            cpB(c + 1, (c + 1) & 1);
            cp_commit();
        }
#pragma unroll
        for (int kh = 0; kh < 2; kh++) {
            uint32_t aH[4][4], aL[4][4];
#pragma unroll
            for (int mt = 0; mt < 4; mt++) {
                uint32_t off = a_base + mt * 2048 + kh * 32;
                ldm_x4(aH[mt][0], aH[mt][1], aH[mt][2], aH[mt][3], stg + SW(off));
                ldm_x4(aL[mt][0], aL[mt][1], aL[mt][2], aL[mt][3], stg + SW(off + 64));
            }
#pragma unroll
            for (int nt = 0; nt < 4; nt++) {
                uint32_t offB = b_base + nt * 1024 + kh * 32;
                uint32_t bh0, bh1;
                ldm_x2(bh0, bh1, stg + 16384 + SW(offB));
#pragma unroll
                for (int mt = 0; mt < 4; mt++) {
                    mma_f16(acc[mt][nt], aH[mt], bh0, bh1);
                    mma_f16(acc[mt][nt], aL[mt], bh0, bh1);
                }
            }
        }
        if (c < 7) {
            stsA((c + 1) & 1);
            cp_wait0();
        }
        __syncthreads();
    }

    __half* C = gm ? g_erh : g_elh;
    const float* bias = gm ? b_dst : b_src;
#pragma unroll
    for (int nt = 0; nt < 4; nt++) {
        int n = wn + nt * 8 + (lane & 3) * 2;
        float b0v = bias[n];
        float b1v = bias[n + 1];
#pragma unroll
        for (int mt = 0; mt < 4; mt++) {
            int m = m0 + wm + mt * 16 + (lane >> 2);
            if (m < NN) {
                __half2 o = __floats2half2_rn(acc[mt][nt][0] + b0v,
                                              acc[mt][nt][1] + b1v);
                *(__half2*)(C + (size_t)m * HD + n) = o;
            }
            if (m + 8 < NN) {
                __half2 o = __floats2half2_rn(acc[mt][nt][2] + b0v,
                                              acc[mt][nt][3] + b1v);
                *(__half2*)(C + (size_t)(m + 8) * HD + n) = o;
            }
        }
    }
}

// ---------------- CSR build ----------------
__global__ void zero_deg_kernel() {
    int i = blockIdx.x * blockDim.x + threadIdx.x;
    if (i < NN) g_deg[i] = 0;
}

__global__ void count_kernel(const int* __restrict__ dst) {
    int e4 = (blockIdx.x * blockDim.x + threadIdx.x) * 4;
    if (e4 < NE) {
        int4 d = *(const int4*)(dst + e4);
        atomicAdd(&g_deg[d.x], 1);
        atomicAdd(&g_deg[d.y], 1);
        atomicAdd(&g_deg[d.z], 1);
        atomicAdd(&g_deg[d.w], 1);
    }
}

__global__ void scan1_kernel() {   // 98 blocks x 1024
    __shared__ int sm[1024];
    int i = blockIdx.x * 1024 + threadIdx.x;
    int v = (i < NN) ? g_deg[i] : 0;
    sm[threadIdx.x] = v;
    __syncthreads();
    for (int off = 1; off < 1024; off <<= 1) {
        int t = (threadIdx.x >= off) ? sm[threadIdx.x - off] : 0;
        __syncthreads();
        sm[threadIdx.x] += t;
        __syncthreads();
    }
    if (i < NN) g_off[i] = sm[threadIdx.x] - v;   // exclusive
    if (threadIdx.x == 1023) g_bsum[blockIdx.x] = sm[1023];
}

__global__ void scan2_kernel() {   // 1 block x 128
    __shared__ int sm[128];
    int v = (threadIdx.x < 98) ? g_bsum[threadIdx.x] : 0;
    sm[threadIdx.x] = v;
    __syncthreads();
    for (int off = 1; off < 128; off <<= 1) {
        int t = (threadIdx.x >= off) ? sm[threadIdx.x - off] : 0;
        __syncthreads();
        sm[threadIdx.x] += t;
        __syncthreads();
    }
    if (threadIdx.x < 98) g_bsum[threadIdx.x] = sm[threadIdx.x] - v;
}

__global__ void scan3_kernel() {   // 98 blocks x 1024
    int i = blockIdx.x * 1024 + threadIdx.x;
    if (i < NN) {
        int o = g_off[i] + g_bsum[i >> 10];
        g_off[i] = o;
        g_cur[i] = o;
    }
    if (i == 0) {
        g_off[NN] = NE;
        g_node_ctr = 0;   // reset work-stealing cursor (runs before node_kernel)
    }
}

__global__ void fill_kernel(const int* __restrict__ src, const int* __restrict__ dst) {
    int e4 = (blockIdx.x * blockDim.x + threadIdx.x) * 4;
    if (e4 < NE) {
        int4 d = *(const int4*)(dst + e4);
        int4 s = *(const int4*)(src + e4);
        int p;
        p = atomicAdd(&g_cur[d.x], 1); g_e[p] = make_int2(e4 + 0, s.x);
        p = atomicAdd(&g_cur[d.y], 1); g_e[p] = make_int2(e4 + 1, s.y);
        p = atomicAdd(&g_cur[d.z], 1); g_e[p] = make_int2(e4 + 2, s.z);
        p = atomicAdd(&g_cur[d.w], 1); g_e[p] = make_int2(e4 + 3, s.w);
    }
}

// ------- pull-based softmax aggregation + fused edge output --------
// Persistent warps + work stealing. 16 lanes per edge, 2 edges/iteration.
// el AND er gathered as fp16 (16B per lane-slice) -> L2-resident hot set.
// Lane layout: sub = lane>>4, h = (lane>>2)&3, q = lane&3, doff = h*32+q*8.
#define WCAP 64
#define NODE_BLOCKS 592
__global__ void __launch_bounds__(256) node_kernel(const float* __restrict__ attn,
                                                   float* __restrict__ out) {
    __shared__ float4 ws[8][WCAP];   // per-CSR-slot weights [4 heads]
    int lane = threadIdx.x & 31;
    int wi   = (threadIdx.x >> 5) & 7;
    const int sub = lane >> 4;
    const int h   = (lane >> 2) & 3;
    const int q   = lane & 3;
    const int doff = h * 32 + q * 8;

    const float4 av0 = *(const float4*)&attn[doff];
    const float4 av1 = *(const float4*)&attn[doff + 4];

    for (;;) {
        int v = 0;
        if (lane == 0) v = atomicAdd(&g_node_ctr, 1);
        v = __shfl_sync(0xffffffffu, v, 0);
        if (v >= NN) return;

        uint4 eraw = *(const uint4*)(g_erh + (size_t)v * HD + doff);
        float2 e0 = __half22float2(*(__half2*)&eraw.x);
        float2 e1 = __half22float2(*(__half2*)&eraw.y);
        float2 e2 = __half22float2(*(__half2*)&eraw.z);
        float2 e3 = __half22float2(*(__half2*)&eraw.w);
        const float4 rv0 = make_float4(e0.x, e0.y, e1.x, e1.y);
        const float4 rv1 = make_float4(e2.x, e2.y, e3.x, e3.y);

        const int beg = g_off[v];
        const int end = g_off[v + 1];
        const int npair = (end - beg + 1) >> 1;

        float lsum = 0.f;
        float4 acc0 = make_float4(0.f, 0.f, 0.f, 0.f);
        float4 acc1 = make_float4(0.f, 0.f, 0.f, 0.f);

        bool cur_ok = (beg + sub) < end;
        bool nxt_ok = (beg + 2 + sub) < end;
        int nxt_src = 0;
        uint4 raw = make_uint4(0u, 0u, 0u, 0u);
        if (cur_ok) {
            int s0 = g_e[beg + sub].y;
            raw = *(const uint4*)(g_elh + (size_t)s0 * HD + doff);
        }
        if (nxt_ok) nxt_src = g_e[beg + 2 + sub].y;

        for (int t = 0; t < npair; t++) {
            uint4 nraw = make_uint4(0u, 0u, 0u, 0u);
            bool ok2 = (beg + 2 * (t + 2) + sub) < end;
            int nn_src = 0;
            if (nxt_ok)
                nraw = *(const uint4*)(g_elh + (size_t)nxt_src * HD + doff);
            if (ok2) nn_src = g_e[beg + 2 * (t + 2) + sub].y;

            float2 a0 = __half22float2(*(__half2*)&raw.x);
            float2 a1 = __half22float2(*(__half2*)&raw.y);
            float2 a2 = __half22float2(*(__half2*)&raw.z);
            float2 a3 = __half22float2(*(__half2*)&raw.w);
            float4 lu0 = make_float4(a0.x, a0.y, a1.x, a1.y);
            float4 lu1 = make_float4(a2.x, a2.y, a3.x, a3.y);

            float p = lrelu(lu0.x + rv0.x) * av0.x;
            p = fmaf(lrelu(lu0.y + rv0.y), av0.y, p);
            p = fmaf(lrelu(lu0.z + rv0.z), av0.z, p);
            p = fmaf(lrelu(lu0.w + rv0.w), av0.w, p);
            p = fmaf(lrelu(lu1.x + rv1.x), av1.x, p);
            p = fmaf(lrelu(lu1.y + rv1.y), av1.y, p);
            p = fmaf(lrelu(lu1.z + rv1.z), av1.z, p);
            p = fmaf(lrelu(lu1.w + rv1.w), av1.w, p);
            p += __shfl_xor_sync(0xffffffffu, p, 1);
            p += __shfl_xor_sync(0xffffffffu, p, 2);

            float ww = cur_ok ? __expf(p) : 0.f;

            if (q == 0 && cur_ok) {
                int pos = 2 * t + sub;
                if (pos < WCAP) ((float*)&ws[wi][pos])[h] = ww;
                else            g_s[(size_t)(beg + pos) * 4 + h] = ww;
            }

            lsum += ww;
            acc0.x = fmaf(ww, lu0.x, acc0.x);
            acc0.y = fmaf(ww, lu0.y, acc0.y);
            acc0.z = fmaf(ww, lu0.z, acc0.z);
            acc0.w = fmaf(ww, lu0.w, acc0.w);
            acc1.x = fmaf(ww, lu1.x, acc1.x);
            acc1.y = fmaf(ww, lu1.y, acc1.y);
            acc1.z = fmaf(ww, lu1.z, acc1.z);
            acc1.w = fmaf(ww, lu1.w, acc1.w);

            raw = nraw;
            cur_ok = nxt_ok;
            nxt_ok = ok2; nxt_src = nn_src;
        }

        // ---- combine the two edge-halves (sub) ----
        acc0.x += __shfl_xor_sync(0xffffffffu, acc0.x, 16);
        acc0.y += __shfl_xor_sync(0xffffffffu, acc0.y, 16);
        acc0.z += __shfl_xor_sync(0xffffffffu, acc0.z, 16);
        acc0.w += __shfl_xor_sync(0xffffffffu, acc0.w, 16);
        acc1.x += __shfl_xor_sync(0xffffffffu, acc1.x, 16);
        acc1.y += __shfl_xor_sync(0xffffffffu, acc1.y, 16);
        acc1.z += __shfl_xor_sync(0xffffffffu, acc1.z, 16);
        acc1.w += __shfl_xor_sync(0xffffffffu, acc1.w, 16);
        lsum   += __shfl_xor_sync(0xffffffffu, lsum, 16);

        float inv = (lsum > 0.f) ? (1.0f / lsum) : 0.f;
        float4 r0, r1;
        r0.x = acc0.x * inv; r0.y = acc0.y * inv;
        r0.z = acc0.z * inv; r0.w = acc0.w * inv;
        r1.x = acc1.x * inv; r1.y = acc1.y * inv;
        r1.z = acc1.z * inv; r1.w = acc1.w * inv;

        // ---- mean over heads: sum across h bits (xor 4, 8) ----
        r0.x += __shfl_xor_sync(0xffffffffu, r0.x, 4);
        r0.y += __shfl_xor_sync(0xffffffffu, r0.y, 4);
        r0.z += __shfl_xor_sync(0xffffffffu, r0.z, 4);
        r0.w += __shfl_xor_sync(0xffffffffu, r0.w, 4);
        r1.x += __shfl_xor_sync(0xffffffffu, r1.x, 4);
        r1.y += __shfl_xor_sync(0xffffffffu, r1.y, 4);
        r1.z += __shfl_xor_sync(0xffffffffu, r1.z, 4);
        r1.w += __shfl_xor_sync(0xffffffffu, r1.w, 4);
        r0.x += __shfl_xor_sync(0xffffffffu, r0.x, 8);
        r0.y += __shfl_xor_sync(0xffffffffu, r0.y, 8);
        r0.z += __shfl_xor_sync(0xffffffffu, r0.z, 8);
        r0.w += __shfl_xor_sync(0xffffffffu, r0.w, 8);
        r1.x += __shfl_xor_sync(0xffffffffu, r1.x, 8);
        r1.y += __shfl_xor_sync(0xffffffffu, r1.y, 8);
        r1.z += __shfl_xor_sync(0xffffffffu, r1.z, 8);
        r1.w += __shfl_xor_sync(0xffffffffu, r1.w, 8);

        if (lane < 4) {   // sub==0, h==0, q=lane
            float4 o0, o1;
            o0.x = r0.x * 0.25f; o0.y = r0.y * 0.25f;
            o0.z = r0.z * 0.25f; o0.w = r0.w * 0.25f;
            o1.x = r1.x * 0.25f; o1.y = r1.y * 0.25f;
            o1.z = r1.z * 0.25f; o1.w = r1.w * 0.25f;
            *(float4*)&out[(size_t)v * 32 + q * 8]     = o0;
            *(float4*)&out[(size_t)v * 32 + q * 8 + 4] = o1;
        }

        // ---- fused per-edge attention mean (phase 2) ----
        __syncwarp();
        float l0 = __shfl_sync(0xffffffffu, lsum, 0);    // head 0
        float l1 = __shfl_sync(0xffffffffu, lsum, 4);    // head 1
        float l2 = __shfl_sync(0xffffffffu, lsum, 8);    // head 2
        float l3 = __shfl_sync(0xffffffffu, lsum, 12);   // head 3
        const float i0 = (l0 > 0.f) ? 0.25f / l0 : 0.f;
        const float i1 = (l1 > 0.f) ? 0.25f / l1 : 0.f;
        const float i2 = (l2 > 0.f) ? 0.25f / l2 : 0.f;
        const float i3 = (l3 > 0.f) ? 0.25f / l3 : 0.f;

        for (int idx = beg + lane; idx < end; idx += 32) {
            int pos = idx - beg;
            float4 w4 = (pos < WCAP) ? ws[wi][pos]
                                     : *(const float4*)&g_s[(size_t)idx * 4];
            int eid = g_e[idx].x;
            float am = w4.x * i0;
            am = fmaf(w4.y, i1, am);
            am = fmaf(w4.z, i2, am);
            am = fmaf(w4.w, i3, am);
            out[(size_t)NN * 32 + eid] = am;
        }
        __syncwarp();   // ws reuse safety before next stolen node
    }
}

// ---------------- launch ----------------
extern "C" void kernel_launch(void* const* d_in, const int* in_sizes, int n_in,
                              void* d_out, int out_size) {
    const float* x     = (const float*)d_in[0];
    const float* w_src = (const float*)d_in[1];
    const float* b_src = (const float*)d_in[2];
    const float* w_dst = (const float*)d_in[3];
    const float* b_dst = (const float*)d_in[4];
    const float* attn  = (const float*)d_in[5];
    const int*   src   = (const int*)d_in[6];
    const int*   dst   = (const int*)d_in[7];
    float* out = (float*)d_out;

    cudaFuncSetAttribute(gemm2_kernel, cudaFuncAttributeMaxDynamicSharedMemorySize, SM_TOT);

    cudaStream_t s2;
    cudaStreamCreateWithFlags(&s2, cudaStreamNonBlocking);
    cudaEvent_t evFork, evJoin;
    cudaEventCreateWithFlags(&evFork, cudaEventDisableTiming);
    cudaEventCreateWithFlags(&evJoin, cudaEventDisableTiming);

    cudaEventRecord(evFork, 0);
    cudaStreamWaitEvent(s2, evFork, 0);

    // stream 0: projection GEMM path
    wsplit_kernel<<<(2 * 8 * 128 * 32 + 255) / 256, 256>>>(w_src, w_dst);
    const int gemm_blocks = (NN + 127) / 128;     // 782
    gemm2_kernel<<<gemm_blocks, 512, SM_TOT>>>(x, b_src, b_dst);

    // stream s2: CSR build path
    zero_deg_kernel<<<(NN + 255) / 256, 256, 0, s2>>>();
    count_kernel<<<(NE / 4 + 255) / 256, 256, 0, s2>>>(dst);
    scan1_kernel<<<98, 1024, 0, s2>>>();
    scan2_kernel<<<1, 128, 0, s2>>>();
    scan3_kernel<<<98, 1024, 0, s2>>>();
    fill_kernel<<<(NE / 4 + 255) / 256, 256, 0, s2>>>(src, dst);

    cudaEventRecord(evJoin, s2);
    cudaStreamWaitEvent(0, evJoin, 0);

    node_kernel<<<NODE_BLOCKS, 256>>>(attn, out);

    cudaEventDestroy(evFork);
    cudaEventDestroy(evJoin);
    cudaStreamDestroy(s2);
}